// round 8
// baseline (speedup 1.0000x reference)
#include <cuda_runtime.h>
#include <cstdint>

// Problem constants
#define NB        32
#define D         768
#define EMBD      768
#define NPOS      196        // 14*14 patches per image
#define ROWS_TOTAL 6272      // NB * NPOS
#define NC0       512
#define NC1       2048
#define NC2       8192
#define OUTSLICE  4816896    // 32*768*196 == 32*3*224*224

// GEMM tiling
#define BM 128
#define BN 128
#define BK 16
#define NT (D / BK)          // 48 k-tiles
#define BROW 140             // padded B smem row stride (words); pad 4 per 32

// ---------------- scratch (static device memory; no allocation) ----------------
__device__ float g_X [ROWS_TOTAL * D];
__device__ float g_D1[ROWS_TOTAL * D];
__device__ float g_D2[ROWS_TOTAL * D];
__device__ float g_norms[NC0 + NC1 + NC2];
__device__ unsigned long long g_best[ROWS_TOTAL];
__device__ int g_cls0[ROWS_TOTAL];
__device__ int g_cls1[ROWS_TOTAL];
__device__ int g_cls2[ROWS_TOTAL];

// ---------------- helpers ----------------
__device__ __forceinline__ void ffma2(unsigned long long& d, unsigned long long a, unsigned long long b) {
    asm("fma.rn.f32x2 %0, %1, %2, %0;" : "+l"(d) : "l"(a), "l"(b));
}
__device__ __forceinline__ unsigned long long swp(unsigned long long v) {
    unsigned long long r;
    asm("{ .reg .b32 lo, hi; mov.b64 {lo, hi}, %1; mov.b64 %0, {hi, lo}; }"
        : "=l"(r) : "l"(v));
    return r;
}
__device__ __forceinline__ void unpk(unsigned long long v, float& lo, float& hi) {
    asm("mov.b64 {%0, %1}, %2;" : "=f"(lo), "=f"(hi) : "l"(v));
}
// order-preserving float -> uint key (ascending)
__device__ __forceinline__ unsigned fkey(float f) {
    unsigned u = __float_as_uint(f);
    return (u & 0x80000000u) ? ~u : (u | 0x80000000u);
}

// ---------------- patchify: data[b,3,224,224] -> X[row, f] ----------------
__global__ void patchify_kernel(const float* __restrict__ data, float* __restrict__ X) {
    int row = blockIdx.x;
    int b  = row / NPOS;
    int p  = row - b * NPOS;
    int ph = p / 14;
    int pw = p - ph * 14;
    const float* src = data + (size_t)b * 3 * 224 * 224;
    float* dst = X + (size_t)row * D;
    for (int f = threadIdx.x; f < D; f += blockDim.x) {
        int c = f >> 8;
        int i = (f >> 4) & 15;
        int j = f & 15;
        dst[f] = src[((size_t)c * 224 + (ph * 16 + i)) * 224 + (pw * 16 + j)];
    }
}

// ---------------- ||c||^2 per center ----------------
__global__ void norms_kernel(const float* __restrict__ C, float* __restrict__ out) {
    int k = blockIdx.x;
    const float* row = C + (size_t)k * D;
    float s = 0.f;
    for (int i = threadIdx.x; i < D; i += 256) {
        float v = row[i];
        s += v * v;
    }
    #pragma unroll
    for (int o = 16; o; o >>= 1) s += __shfl_xor_sync(0xffffffffu, s, o);
    __shared__ float red[8];
    if ((threadIdx.x & 31) == 0) red[threadIdx.x >> 5] = s;
    __syncthreads();
    if (threadIdx.x == 0) {
        float t = 0.f;
        #pragma unroll
        for (int w = 0; w < 8; w++) t += red[w];
        out[k] = t;
    }
}

// ---------------- init best to +inf key ----------------
__global__ void init_best_kernel(unsigned long long* __restrict__ best) {
    int i = blockIdx.x * 256 + threadIdx.x;
    if (i < ROWS_TOTAL) best[i] = ~0ull;
}

// ---------------- fused GEMM + argmin (128x128 tile, double-buffered) ----------------
// scores[r, n] = norms[n] - 2 * dot(X[r], C[n]); atomicMin of packed (key, idx)
__global__ __launch_bounds__(256, 2) void score_kernel(
    const float* __restrict__ X, const float* __restrict__ C,
    const float* __restrict__ norms, unsigned long long* __restrict__ best)
{
    __shared__ __align__(16) float As[2][BK][BM];
    __shared__ __align__(16) float Bs[2][BK][BROW];
    __shared__ unsigned long long red[BM];

    const int tid = threadIdx.x;
    const int tx = tid & 15;             // 8 N-cols each: n = tx*8 .. tx*8+7
    const int ty = tid >> 4;             // 8 M-rows each: m = ty*8 .. ty*8+7
    const int rowTile = blockIdx.x * BM;
    const int colTile = blockIdx.y * BN;

    // global->smem load mapping (float4 per thread)
    const int ar0  = tid >> 2;           // 0..63
    const int ak   = (tid & 3) << 2;     // k offset {0,4,8,12}
    const int aswz = (tid & 3) << 3;     // A XOR swizzle {0,8,16,24}
    const int ca   = ar0 ^ aswz;
    const int ca2  = (ar0 + 64) ^ aswz;

    // B store word offsets (gap-padded layout: w(n) = n + 4*(n>>5))
    const int bw0 = ar0 + ((ar0 >> 5) << 2);
    const int bw1 = (ar0 + 64) + (((ar0 + 64) >> 5) << 2);
    // B read word offsets (two LDS.128 per kk)
    const int rb0 = tx * 8;
    const int rw0 = rb0 + ((rb0 >> 5) << 2);
    const int rw1 = rw0 + 4;

    // diagonal-pair accumulators:
    // accD[p][q] = (s[2p][2q],   s[2p+1][2q+1])
    // accX[p][q] = (s[2p][2q+1], s[2p+1][2q]  )   (rows rel ty*8, cols rel tx*8)
    unsigned long long accD[4][4], accX[4][4];
    #pragma unroll
    for (int p = 0; p < 4; p++)
        #pragma unroll
        for (int q = 0; q < 4; q++) { accD[p][q] = 0ull; accX[p][q] = 0ull; }

    const float* Xbase  = X + (size_t)(rowTile + ar0) * D + ak;
    const float* Xbase2 = Xbase + (size_t)64 * D;
    const float* Cb0    = C + (size_t)(colTile + ar0) * D + ak;
    const float* Cb1    = Cb0 + (size_t)64 * D;

    // prologue: tile 0 -> regs -> buf 0
    float4 pa0 = *(const float4*)(Xbase);
    float4 pa1 = *(const float4*)(Xbase2);
    float4 pb0 = *(const float4*)(Cb0);
    float4 pb1 = *(const float4*)(Cb1);
    {
        As[0][ak + 0][ca] = pa0.x; As[0][ak + 1][ca] = pa0.y;
        As[0][ak + 2][ca] = pa0.z; As[0][ak + 3][ca] = pa0.w;
        As[0][ak + 0][ca2] = pa1.x; As[0][ak + 1][ca2] = pa1.y;
        As[0][ak + 2][ca2] = pa1.z; As[0][ak + 3][ca2] = pa1.w;
        Bs[0][ak + 0][bw0] = pb0.x; Bs[0][ak + 1][bw0] = pb0.y;
        Bs[0][ak + 2][bw0] = pb0.z; Bs[0][ak + 3][bw0] = pb0.w;
        Bs[0][ak + 0][bw1] = pb1.x; Bs[0][ak + 1][bw1] = pb1.y;
        Bs[0][ak + 2][bw1] = pb1.z; Bs[0][ak + 3][bw1] = pb1.w;
    }

    for (int t = 0; t < NT; t++) {
        const int cur = t & 1;
        // prefetch tile t+1 into registers
        if (t + 1 < NT) {
            int ko = (t + 1) * BK;
            pa0 = *(const float4*)(Xbase  + ko);
            pa1 = *(const float4*)(Xbase2 + ko);
            pb0 = *(const float4*)(Cb0 + ko);
            pb1 = *(const float4*)(Cb1 + ko);
        }
        __syncthreads();   // buf[cur] stored by all; buf[cur^1] fully consumed
        if (t + 1 < NT) {
            const int nx = cur ^ 1;
            As[nx][ak + 0][ca] = pa0.x; As[nx][ak + 1][ca] = pa0.y;
            As[nx][ak + 2][ca] = pa0.z; As[nx][ak + 3][ca] = pa0.w;
            As[nx][ak + 0][ca2] = pa1.x; As[nx][ak + 1][ca2] = pa1.y;
            As[nx][ak + 2][ca2] = pa1.z; As[nx][ak + 3][ca2] = pa1.w;
            Bs[nx][ak + 0][bw0] = pb0.x; Bs[nx][ak + 1][bw0] = pb0.y;
            Bs[nx][ak + 2][bw0] = pb0.z; Bs[nx][ak + 3][bw0] = pb0.w;
            Bs[nx][ak + 0][bw1] = pb1.x; Bs[nx][ak + 1][bw1] = pb1.y;
            Bs[nx][ak + 2][bw1] = pb1.z; Bs[nx][ak + 3][bw1] = pb1.w;
        }

        // compute from buf[cur]
        #pragma unroll
        for (int kk = 0; kk < BK; kk++) {
            const int offs = ((kk >> 2) & 3) << 3;
            const int sa = (ty * 8) ^ offs;
            ulonglong2 a01 = *(const ulonglong2*)&As[cur][kk][sa];
            ulonglong2 a23 = *(const ulonglong2*)&As[cur][kk][sa + 4];
            ulonglong2 b01 = *(const ulonglong2*)&Bs[cur][kk][rw0];
            ulonglong2 b23 = *(const ulonglong2*)&Bs[cur][kk][rw1];
            unsigned long long A0 = a01.x, A1 = a01.y, A2 = a23.x, A3 = a23.y;
            unsigned long long B0 = b01.x, B1 = b01.y, B2 = b23.x, B3 = b23.y;
            unsigned long long S0 = swp(B0), S1 = swp(B1), S2 = swp(B2), S3 = swp(B3);
            ffma2(accD[0][0], A0, B0); ffma2(accX[0][0], A0, S0);
            ffma2(accD[0][1], A0, B1); ffma2(accX[0][1], A0, S1);
            ffma2(accD[0][2], A0, B2); ffma2(accX[0][2], A0, S2);
            ffma2(accD[0][3], A0, B3); ffma2(accX[0][3], A0, S3);
            ffma2(accD[1][0], A1, B0); ffma2(accX[1][0], A1, S0);
            ffma2(accD[1][1], A1, B1); ffma2(accX[1][1], A1, S1);
            ffma2(accD[1][2], A1, B2); ffma2(accX[1][2], A1, S2);
            ffma2(accD[1][3], A1, B3); ffma2(accX[1][3], A1, S3);
            ffma2(accD[2][0], A2, B0); ffma2(accX[2][0], A2, S0);
            ffma2(accD[2][1], A2, B1); ffma2(accX[2][1], A2, S1);
            ffma2(accD[2][2], A2, B2); ffma2(accX[2][2], A2, S2);
            ffma2(accD[2][3], A2, B3); ffma2(accX[2][3], A2, S3);
            ffma2(accD[3][0], A3, B0); ffma2(accX[3][0], A3, S0);
            ffma2(accD[3][1], A3, B1); ffma2(accX[3][1], A3, S1);
            ffma2(accD[3][2], A3, B2); ffma2(accX[3][2], A3, S2);
            ffma2(accD[3][3], A3, B3); ffma2(accX[3][3], A3, S3);
        }
    }

    // per-thread argmin over its 8 columns, then block/global reduction
    float nrm[8];
    #pragma unroll
    for (int j = 0; j < 8; j++) nrm[j] = norms[colTile + tx * 8 + j];

    if (tid < BM) red[tid] = ~0ull;
    __syncthreads();

    #pragma unroll
    for (int p = 0; p < 4; p++) {
        // reconstruct row scores from diagonal pairs
        float sr0[8], sr1[8];   // rows ty*8+2p, ty*8+2p+1
        #pragma unroll
        for (int q = 0; q < 4; q++) {
            float dlo, dhi, xlo, xhi;
            unpk(accD[p][q], dlo, dhi);
            unpk(accX[p][q], xlo, xhi);
            sr0[2 * q]     = dlo;   // (2p, 2q)
            sr0[2 * q + 1] = xlo;   // (2p, 2q+1)
            sr1[2 * q]     = xhi;   // (2p+1, 2q)
            sr1[2 * q + 1] = dhi;   // (2p+1, 2q+1)
        }
        {
            float bs = nrm[0] - 2.f * sr0[0];
            int bn = 0;
            #pragma unroll
            for (int j = 1; j < 8; j++) {
                float s = nrm[j] - 2.f * sr0[j];
                if (s < bs) { bs = s; bn = j; }
            }
            unsigned long long key =
                ((unsigned long long)fkey(bs) << 32) | (unsigned)(colTile + tx * 8 + bn);
            atomicMin(&red[ty * 8 + 2 * p], key);
        }
        {
            float bs = nrm[0] - 2.f * sr1[0];
            int bn = 0;
            #pragma unroll
            for (int j = 1; j < 8; j++) {
                float s = nrm[j] - 2.f * sr1[j];
                if (s < bs) { bs = s; bn = j; }
            }
            unsigned long long key =
                ((unsigned long long)fkey(bs) << 32) | (unsigned)(colTile + tx * 8 + bn);
            atomicMin(&red[ty * 8 + 2 * p + 1], key);
        }
    }
    __syncthreads();
    if (tid < BM) atomicMin(&best[rowTile + tid], red[tid]);
}

// ---------------- gather: diff = prev - C[cls]; record cls ----------------
__global__ void gather_kernel(const float* __restrict__ prev, const float* __restrict__ C,
                              const unsigned long long* __restrict__ best,
                              float* __restrict__ outd, int* __restrict__ cls)
{
    int row = blockIdx.x;
    int k = (int)(best[row] & 0xffffffffull);
    if (threadIdx.x == 0) cls[row] = k;
    const float4* pr = (const float4*)(prev + (size_t)row * D);
    const float4* cr = (const float4*)(C + (size_t)k * D);
    float4* orow = (float4*)(outd + (size_t)row * D);
    for (int f = threadIdx.x; f < D / 4; f += blockDim.x) {
        float4 a = pr[f];
        float4 b = cr[f];
        orow[f] = make_float4(a.x - b.x, a.y - b.y, a.z - b.z, a.w - b.w);
    }
}

// ---------------- embed: out[b, e, ph, pw] = e0[cls0]+e1[cls1]+e2[cls2] ----------------
__global__ void embed_kernel(const float* __restrict__ e0, const float* __restrict__ e1,
                             const float* __restrict__ e2,
                             const int* __restrict__ cls0, const int* __restrict__ cls1,
                             const int* __restrict__ cls2, float* __restrict__ out)
{
    int b = blockIdx.x;
    int ebase = blockIdx.y * 8;
    __shared__ int s0[NPOS], s1[NPOS], s2[NPOS];
    for (int p = threadIdx.x; p < NPOS; p += blockDim.x) {
        int r = b * NPOS + p;
        s0[p] = cls0[r]; s1[p] = cls1[r]; s2[p] = cls2[r];
    }
    __syncthreads();
    for (int idx = threadIdx.x; idx < 8 * NPOS; idx += blockDim.x) {
        int e = ebase + idx / NPOS;
        int p = idx - (idx / NPOS) * NPOS;
        out[((size_t)b * EMBD + e) * NPOS + p] =
            e0[(size_t)s0[p] * EMBD + e] +
            e1[(size_t)s1[p] * EMBD + e] +
            e2[(size_t)s2[p] * EMBD + e];
    }
}

// ---------------- img_sum: out[b,c,h,w] = X - finalDiff (image layout) ----------------
__global__ void img_kernel(const float* __restrict__ X, const float* __restrict__ Df,
                           float* __restrict__ out)
{
    int b = blockIdx.x, c = blockIdx.y, h = blockIdx.z;
    int w = threadIdx.x;
    int row = b * NPOS + (h >> 4) * 14 + (w >> 4);
    int f = (c << 8) + ((h & 15) << 4) + (w & 15);
    size_t o = (((size_t)b * 3 + c) * 224 + h) * 224 + w;
    size_t s = (size_t)row * D + f;
    out[o] = X[s] - Df[s];
}

// ---------------- diff_out: out[b, f, ph, pw] = finalDiff[row, f] ----------------
__global__ void diffout_kernel(const float* __restrict__ Df, float* __restrict__ out)
{
    int b = blockIdx.x;
    int fbase = blockIdx.y * 8;
    for (int idx = threadIdx.x; idx < 8 * NPOS; idx += blockDim.x) {
        int f = fbase + idx / NPOS;
        int p = idx - (idx / NPOS) * NPOS;
        out[((size_t)b * D + f) * NPOS + p] = Df[((size_t)(b * NPOS + p)) * D + f];
    }
}

// ---------------- launch ----------------
extern "C" void kernel_launch(void* const* d_in, const int* in_sizes, int n_in,
                              void* d_out, int out_size)
{
    const float* data = (const float*)d_in[0];
    const float* c0 = (const float*)d_in[1];
    const float* c1 = (const float*)d_in[2];
    const float* c2 = (const float*)d_in[3];
    const float* e0 = (const float*)d_in[4];
    const float* e1 = (const float*)d_in[5];
    const float* e2 = (const float*)d_in[6];
    float* out = (float*)d_out;

    void *pX, *pD1, *pD2, *pN, *pB, *pC0, *pC1, *pC2;
    cudaGetSymbolAddress(&pX, g_X);
    cudaGetSymbolAddress(&pD1, g_D1);
    cudaGetSymbolAddress(&pD2, g_D2);
    cudaGetSymbolAddress(&pN, g_norms);
    cudaGetSymbolAddress(&pB, g_best);
    cudaGetSymbolAddress(&pC0, g_cls0);
    cudaGetSymbolAddress(&pC1, g_cls1);
    cudaGetSymbolAddress(&pC2, g_cls2);
    float* X  = (float*)pX;
    float* D1 = (float*)pD1;
    float* D2 = (float*)pD2;
    float* nrm = (float*)pN;
    unsigned long long* best = (unsigned long long*)pB;
    int* cls0 = (int*)pC0;
    int* cls1 = (int*)pC1;
    int* cls2 = (int*)pC2;

    patchify_kernel<<<ROWS_TOTAL, 256>>>(data, X);
    norms_kernel<<<NC0, 256>>>(c0, nrm);
    norms_kernel<<<NC1, 256>>>(c1, nrm + NC0);
    norms_kernel<<<NC2, 256>>>(c2, nrm + NC0 + NC1);

    // stage 0
    init_best_kernel<<<(ROWS_TOTAL + 255) / 256, 256>>>(best);
    score_kernel<<<dim3(ROWS_TOTAL / BM, NC0 / BN), 256>>>(X, c0, nrm, best);
    gather_kernel<<<ROWS_TOTAL, 192>>>(X, c0, best, D1, cls0);

    // stage 1
    init_best_kernel<<<(ROWS_TOTAL + 255) / 256, 256>>>(best);
    score_kernel<<<dim3(ROWS_TOTAL / BM, NC1 / BN), 256>>>(D1, c1, nrm + NC0, best);
    gather_kernel<<<ROWS_TOTAL, 192>>>(D1, c1, best, D2, cls1);

    // stage 2
    init_best_kernel<<<(ROWS_TOTAL + 255) / 256, 256>>>(best);
    score_kernel<<<dim3(ROWS_TOTAL / BM, NC2 / BN), 256>>>(D2, c2, nrm + NC0 + NC1, best);
    gather_kernel<<<ROWS_TOTAL, 192>>>(D2, c2, best, D1, cls2);

    // outputs: [embed | img_sum | diff_out]
    embed_kernel<<<dim3(NB, EMBD / 8), 256>>>(e0, e1, e2, cls0, cls1, cls2, out);
    img_kernel<<<dim3(NB, 3, 224), 224>>>(X, D1, out + OUTSLICE);
    diffout_kernel<<<dim3(NB, D / 8), 256>>>(D1, out + 2 * OUTSLICE);
}

// round 9
// speedup vs baseline: 1.1193x; 1.1193x over previous
#include <cuda_runtime.h>
#include <cstdint>

// Problem constants
#define NB        32
#define D         768
#define EMBD      768
#define NPOS      196        // 14*14 patches per image
#define ROWS_TOTAL 6272      // NB * NPOS = 49 * 128
#define NC0       512
#define NC1       2048
#define NC2       8192
#define OUTSLICE  4816896    // 32*768*196 == 32*3*224*224

// GEMM tiling
#define BM 128
#define BN 128
#define BK 32
#define NTL (D / BK)         // 24 k-tiles
#define BROW 140             // padded B smem row stride (words); pad 4 per 32

// dynamic smem layout (words)
#define AS_WORDS (2 * BK * BM)            // 8192
#define BS_WORDS (2 * BK * BROW)          // 8960
#define RED_OFF_B ((AS_WORDS + BS_WORDS) * 4)   // 68608
#define SMEM_TOTAL (RED_OFF_B + BM * 8)         // 69632

// ---------------- scratch (static device memory; no allocation) ----------------
__device__ float g_X [ROWS_TOTAL * D];
__device__ float g_D1[ROWS_TOTAL * D];
__device__ float g_D2[ROWS_TOTAL * D];
__device__ float g_Xt[(size_t)D * ROWS_TOTAL];   // transposed A operand
__device__ float g_Ct[(size_t)D * NC2];          // transposed C operand (per stage reuse)
__device__ float g_norms[NC2];                   // per-stage reuse
__device__ unsigned long long g_best[ROWS_TOTAL];
__device__ int g_cls0[ROWS_TOTAL];
__device__ int g_cls1[ROWS_TOTAL];
__device__ int g_cls2[ROWS_TOTAL];

// ---------------- helpers ----------------
__device__ __forceinline__ uint32_t smem_u32(const void* p) {
    uint32_t a;
    asm("{ .reg .u64 t; cvta.to.shared.u64 t, %1; cvt.u32.u64 %0, t; }" : "=r"(a) : "l"(p));
    return a;
}
__device__ __forceinline__ unsigned long long pk2(float v) {
    unsigned long long r;
    asm("mov.b64 %0, {%1, %1};" : "=l"(r) : "f"(v));
    return r;
}
__device__ __forceinline__ void ffma2(unsigned long long& d, unsigned long long a, unsigned long long b) {
    asm("fma.rn.f32x2 %0, %1, %2, %0;" : "+l"(d) : "l"(a), "l"(b));
}
__device__ __forceinline__ void unpk(unsigned long long v, float& lo, float& hi) {
    asm("mov.b64 {%0, %1}, %2;" : "=f"(lo), "=f"(hi) : "l"(v));
}
__device__ __forceinline__ unsigned fkey(float f) {
    unsigned u = __float_as_uint(f);
    return (u & 0x80000000u) ? ~u : (u | 0x80000000u);
}
__device__ __forceinline__ void cp16(uint32_t d, const void* s) {
    asm volatile("cp.async.cg.shared.global [%0], [%1], 16;" :: "r"(d), "l"(s));
}
#define CP_COMMIT() asm volatile("cp.async.commit_group;" ::: "memory")
#define CP_WAIT1()  asm volatile("cp.async.wait_group 1;" ::: "memory")
#define CP_WAIT0()  asm volatile("cp.async.wait_group 0;" ::: "memory")

// ---------------- patchify: data[b,3,224,224] -> X[row, f]; zero best ----------------
__global__ void patchify_kernel(const float* __restrict__ data, float* __restrict__ X,
                                unsigned long long* __restrict__ best) {
    int row = blockIdx.x;
    if (threadIdx.x == 0) best[row] = ~0ull;
    int b  = row / NPOS;
    int p  = row - b * NPOS;
    int ph = p / 14;
    int pw = p - ph * 14;
    const float* src = data + (size_t)b * 3 * 224 * 224;
    float* dst = X + (size_t)row * D;
    for (int f = threadIdx.x; f < D; f += blockDim.x) {
        int c = f >> 8;
        int i = (f >> 4) & 15;
        int j = f & 15;
        dst[f] = src[((size_t)c * 224 + (ph * 16 + i)) * 224 + (pw * 16 + j)];
    }
}

// ---------------- transpose: src[R][768] -> dst[768][R] (R = ROWS_TOTAL) ----------------
__global__ void trans_kernel(const float* __restrict__ src, float* __restrict__ dst) {
    __shared__ float t[32][33];
    int bx = blockIdx.x * 32;   // k base
    int by = blockIdx.y * 32;   // row base
    #pragma unroll
    for (int j = 0; j < 4; j++)
        t[threadIdx.y + j * 8][threadIdx.x] =
            src[(size_t)(by + threadIdx.y + j * 8) * D + bx + threadIdx.x];
    __syncthreads();
    #pragma unroll
    for (int j = 0; j < 4; j++)
        dst[(size_t)(bx + threadIdx.y + j * 8) * ROWS_TOTAL + by + threadIdx.x] =
            t[threadIdx.x][threadIdx.y + j * 8];
}

// ---------------- cprep: C[Kn][768] -> Ct[768][Kn] + norms (deterministic) ----------------
#define CPRC 256
__global__ __launch_bounds__(256) void cprep_kernel(const float* __restrict__ C,
                                                    float* __restrict__ Ct,
                                                    float* __restrict__ norms, int Kn) {
    __shared__ float t[32][CPRC + 1];
    int n0 = blockIdx.x * 32;
    int tid = threadIdx.x;
    int r = tid >> 3;        // 0..31 (row within block)
    int q = tid & 7;         // 0..7
    float nrm = 0.f;
    for (int cc = 0; cc < D / CPRC; cc++) {
        #pragma unroll
        for (int j = 0; j < 8; j++) {
            int c4 = (q + 8 * j) * 4;
            float4 v = *(const float4*)(C + (size_t)(n0 + r) * D + cc * CPRC + c4);
            t[r][c4 + 0] = v.x; t[r][c4 + 1] = v.y;
            t[r][c4 + 2] = v.z; t[r][c4 + 3] = v.w;
            nrm += v.x * v.x + v.y * v.y + v.z * v.z + v.w * v.w;
        }
        __syncthreads();
        int n = tid & 31;
        int k0 = tid >> 5;   // 0..7
        #pragma unroll
        for (int jj = 0; jj < 32; jj++) {
            int kloc = k0 + 8 * jj;
            Ct[(size_t)(cc * CPRC + kloc) * Kn + n0 + n] = t[n][kloc];
        }
        __syncthreads();
    }
    nrm += __shfl_down_sync(0xffffffffu, nrm, 4, 8);
    nrm += __shfl_down_sync(0xffffffffu, nrm, 2, 8);
    nrm += __shfl_down_sync(0xffffffffu, nrm, 1, 8);
    if (q == 0) norms[n0 + r] = nrm;
}

// ---------------- fused GEMM + argmin (128x128 tile, cp.async, BK=32) ----------------
extern __shared__ char smem_raw[];
__global__ __launch_bounds__(256, 2) void score_kernel(
    const float* __restrict__ Xt, const float* __restrict__ Ct, int Kn,
    const float* __restrict__ norms, unsigned long long* __restrict__ best)
{
    float* sw = (float*)smem_raw;
    unsigned long long* red = (unsigned long long*)(smem_raw + RED_OFF_B);
    const uint32_t sb = smem_u32(smem_raw);

    const int tid = threadIdx.x;
    const int tx = tid & 15;             // 8 N-cols each
    const int ty = tid >> 4;             // 8 M-rows each
    const int rowTile = blockIdx.x * BM;
    const int colTile = blockIdx.y * BN;

    // cp.async mapping: kr = k-row within tile, cA = 16B chunk group
    const int kr = tid >> 3;             // 0..31
    const int cA = tid & 7;              // 0..7

    // B read word offsets (gap-pad w(n) = n + 4*(n>>5))
    const int rw0 = 8 * tx + 4 * (tx >> 2);

    unsigned long long acc[4][8];
    #pragma unroll
    for (int i = 0; i < 4; i++)
        #pragma unroll
        for (int j = 0; j < 8; j++) acc[i][j] = 0ull;

    #define ISSUE(t_) do { \
        const int buf_ = (t_) & 1; \
        const int kt_ = (t_) * BK; \
        const uint32_t aw_ = sb + (uint32_t)(buf_ * BK * BM) * 4 + (uint32_t)(kr * BM) * 4; \
        const uint32_t bw_ = sb + (uint32_t)(AS_WORDS + buf_ * BK * BROW) * 4 + (uint32_t)(kr * BROW) * 4; \
        const float* as_ = Xt + (size_t)(kt_ + kr) * ROWS_TOTAL + rowTile; \
        const float* bs_ = Ct + (size_t)(kt_ + kr) * Kn + colTile; \
        _Pragma("unroll") \
        for (int j_ = 0; j_ < 4; j_++) { \
            int n4_ = (cA + 8 * j_) * 4; \
            cp16(aw_ + (uint32_t)n4_ * 4, as_ + n4_); \
            cp16(bw_ + (uint32_t)(n4_ + 4 * (n4_ >> 5)) * 4, bs_ + n4_); \
        } \
    } while (0)

    ISSUE(0); CP_COMMIT();
    ISSUE(1); CP_COMMIT();

    for (int t = 0; t < NTL; t++) {
        if (t + 1 < NTL) CP_WAIT1(); else CP_WAIT0();
        __syncthreads();
        const float* sA = sw + (t & 1) * (BK * BM);
        const float* sB = sw + AS_WORDS + (t & 1) * (BK * BROW);

        #pragma unroll 16
        for (int kk = 0; kk < BK; kk++) {
            ulonglong2 a01 = *(const ulonglong2*)(sA + kk * BM + ty * 8);
            ulonglong2 a23 = *(const ulonglong2*)(sA + kk * BM + ty * 8 + 4);
            float4 bv0 = *(const float4*)(sB + kk * BROW + rw0);
            float4 bv1 = *(const float4*)(sB + kk * BROW + rw0 + 4);
            unsigned long long b[8];
            b[0] = pk2(bv0.x); b[1] = pk2(bv0.y); b[2] = pk2(bv0.z); b[3] = pk2(bv0.w);
            b[4] = pk2(bv1.x); b[5] = pk2(bv1.y); b[6] = pk2(bv1.z); b[7] = pk2(bv1.w);
            unsigned long long A0 = a01.x, A1 = a01.y, A2v = a23.x, A3 = a23.y;
            #pragma unroll
            for (int j = 0; j < 8; j++) {
                ffma2(acc[0][j], A0, b[j]);
                ffma2(acc[1][j], A1, b[j]);
                ffma2(acc[2][j], A2v, b[j]);
                ffma2(acc[3][j], A3, b[j]);
            }
        }
        __syncthreads();
        if (t + 2 < NTL) { ISSUE(t + 2); CP_COMMIT(); }
    }
    #undef ISSUE

    // per-thread argmin over its 8 columns, then block/global reduction
    float nrm[8];
    #pragma unroll
    for (int j = 0; j < 8; j++) nrm[j] = norms[colTile + tx * 8 + j];

    if (tid < BM) red[tid] = ~0ull;
    __syncthreads();

    #pragma unroll
    for (int i = 0; i < 4; i++) {
        float lo[8], hi[8];
        #pragma unroll
        for (int j = 0; j < 8; j++) unpk(acc[i][j], lo[j], hi[j]);
        {
            float bs = nrm[0] - 2.f * lo[0];
            int bn = 0;
            #pragma unroll
            for (int j = 1; j < 8; j++) {
                float s = nrm[j] - 2.f * lo[j];
                if (s < bs) { bs = s; bn = j; }
            }
            unsigned long long key =
                ((unsigned long long)fkey(bs) << 32) | (unsigned)(colTile + tx * 8 + bn);
            atomicMin(&red[ty * 8 + 2 * i], key);
        }
        {
            float bs = nrm[0] - 2.f * hi[0];
            int bn = 0;
            #pragma unroll
            for (int j = 1; j < 8; j++) {
                float s = nrm[j] - 2.f * hi[j];
                if (s < bs) { bs = s; bn = j; }
            }
            unsigned long long key =
                ((unsigned long long)fkey(bs) << 32) | (unsigned)(colTile + tx * 8 + bn);
            atomicMin(&red[ty * 8 + 2 * i + 1], key);
        }
    }
    __syncthreads();
    if (tid < BM) atomicMin(&best[rowTile + tid], red[tid]);
}

// ---------------- gather: diff = prev - C[cls]; record cls; reset best ----------------
__global__ void gather_kernel(const float* __restrict__ prev, const float* __restrict__ C,
                              unsigned long long* __restrict__ best,
                              float* __restrict__ outd, int* __restrict__ cls)
{
    int row = blockIdx.x;
    int k = (int)(best[row] & 0xffffffffull);
    if (threadIdx.x == 0) { cls[row] = k; best[row] = ~0ull; }
    const float4* pr = (const float4*)(prev + (size_t)row * D);
    const float4* cr = (const float4*)(C + (size_t)k * D);
    float4* orow = (float4*)(outd + (size_t)row * D);
    for (int f = threadIdx.x; f < D / 4; f += blockDim.x) {
        float4 a = pr[f];
        float4 b = cr[f];
        orow[f] = make_float4(a.x - b.x, a.y - b.y, a.z - b.z, a.w - b.w);
    }
}

// ---------------- embed ----------------
__global__ void embed_kernel(const float* __restrict__ e0, const float* __restrict__ e1,
                             const float* __restrict__ e2,
                             const int* __restrict__ cls0, const int* __restrict__ cls1,
                             const int* __restrict__ cls2, float* __restrict__ out)
{
    int b = blockIdx.x;
    int ebase = blockIdx.y * 8;
    __shared__ int s0[NPOS], s1[NPOS], s2[NPOS];
    for (int p = threadIdx.x; p < NPOS; p += blockDim.x) {
        int r = b * NPOS + p;
        s0[p] = cls0[r]; s1[p] = cls1[r]; s2[p] = cls2[r];
    }
    __syncthreads();
    for (int idx = threadIdx.x; idx < 8 * NPOS; idx += blockDim.x) {
        int e = ebase + idx / NPOS;
        int p = idx - (idx / NPOS) * NPOS;
        out[((size_t)b * EMBD + e) * NPOS + p] =
            e0[(size_t)s0[p] * EMBD + e] +
            e1[(size_t)s1[p] * EMBD + e] +
            e2[(size_t)s2[p] * EMBD + e];
    }
}

// ---------------- img_sum ----------------
__global__ void img_kernel(const float* __restrict__ X, const float* __restrict__ Df,
                           float* __restrict__ out)
{
    int b = blockIdx.x, c = blockIdx.y, h = blockIdx.z;
    int w = threadIdx.x;
    int row = b * NPOS + (h >> 4) * 14 + (w >> 4);
    int f = (c << 8) + ((h & 15) << 4) + (w & 15);
    size_t o = (((size_t)b * 3 + c) * 224 + h) * 224 + w;
    size_t s = (size_t)row * D + f;
    out[o] = X[s] - Df[s];
}

// ---------------- diff_out ----------------
__global__ void diffout_kernel(const float* __restrict__ Df, float* __restrict__ out)
{
    int b = blockIdx.x;
    int fbase = blockIdx.y * 8;
    for (int idx = threadIdx.x; idx < 8 * NPOS; idx += blockDim.x) {
        int f = fbase + idx / NPOS;
        int p = idx - (idx / NPOS) * NPOS;
        out[((size_t)b * D + f) * NPOS + p] = Df[((size_t)(b * NPOS + p)) * D + f];
    }
}

// ---------------- launch ----------------
extern "C" void kernel_launch(void* const* d_in, const int* in_sizes, int n_in,
                              void* d_out, int out_size)
{
    const float* data = (const float*)d_in[0];
    const float* c0 = (const float*)d_in[1];
    const float* c1 = (const float*)d_in[2];
    const float* c2 = (const float*)d_in[3];
    const float* e0 = (const float*)d_in[4];
    const float* e1 = (const float*)d_in[5];
    const float* e2 = (const float*)d_in[6];
    float* out = (float*)d_out;

    void *pX, *pD1, *pD2, *pXt, *pCt, *pN, *pB, *pC0, *pC1, *pC2;
    cudaGetSymbolAddress(&pX, g_X);
    cudaGetSymbolAddress(&pD1, g_D1);
    cudaGetSymbolAddress(&pD2, g_D2);
    cudaGetSymbolAddress(&pXt, g_Xt);
    cudaGetSymbolAddress(&pCt, g_Ct);
    cudaGetSymbolAddress(&pN, g_norms);
    cudaGetSymbolAddress(&pB, g_best);
    cudaGetSymbolAddress(&pC0, g_cls0);
    cudaGetSymbolAddress(&pC1, g_cls1);
    cudaGetSymbolAddress(&pC2, g_cls2);
    float* X  = (float*)pX;
    float* D1 = (float*)pD1;
    float* D2 = (float*)pD2;
    float* Xt = (float*)pXt;
    float* Ct = (float*)pCt;
    float* nrm = (float*)pN;
    unsigned long long* best = (unsigned long long*)pB;
    int* cls0 = (int*)pC0;
    int* cls1 = (int*)pC1;
    int* cls2 = (int*)pC2;

    cudaFuncSetAttribute(score_kernel, cudaFuncAttributeMaxDynamicSharedMemorySize, SMEM_TOTAL);

    dim3 t32(32, 8);
    dim3 tgrid(D / 32, ROWS_TOTAL / 32);

    // stage 0  (launch order puts score_kernel at slot 4 for the ncu window)
    patchify_kernel<<<ROWS_TOTAL, 256>>>(data, X, best);
    trans_kernel<<<tgrid, t32>>>(X, Xt);
    cprep_kernel<<<NC0 / 32, 256>>>(c0, Ct, nrm, NC0);
    score_kernel<<<dim3(ROWS_TOTAL / BM, NC0 / BN), 256, SMEM_TOTAL>>>(Xt, Ct, NC0, nrm, best);
    gather_kernel<<<ROWS_TOTAL, 192>>>(X, c0, best, D1, cls0);

    // stage 1
    trans_kernel<<<tgrid, t32>>>(D1, Xt);
    cprep_kernel<<<NC1 / 32, 256>>>(c1, Ct, nrm, NC1);
    score_kernel<<<dim3(ROWS_TOTAL / BM, NC1 / BN), 256, SMEM_TOTAL>>>(Xt, Ct, NC1, nrm, best);
    gather_kernel<<<ROWS_TOTAL, 192>>>(D1, c1, best, D2, cls1);

    // stage 2
    trans_kernel<<<tgrid, t32>>>(D2, Xt);
    cprep_kernel<<<NC2 / 32, 256>>>(c2, Ct, nrm, NC2);
    score_kernel<<<dim3(ROWS_TOTAL / BM, NC2 / BN), 256, SMEM_TOTAL>>>(Xt, Ct, NC2, nrm, best);
    gather_kernel<<<ROWS_TOTAL, 192>>>(D2, c2, best, D1, cls2);

    // outputs: [embed | img_sum | diff_out]
    embed_kernel<<<dim3(NB, EMBD / 8), 256>>>(e0, e1, e2, cls0, cls1, cls2, out);
    img_kernel<<<dim3(NB, 3, 224), 224>>>(X, D1, out + OUTSLICE);
    diffout_kernel<<<dim3(NB, D / 8), 256>>>(D1, out + 2 * OUTSLICE);
}